// round 11
// baseline (speedup 1.0000x reference)
#include <cuda_runtime.h>
#include <math.h>

#define Bc 2
#define Hc 1080
#define Wc 1920
#define Kc 2048
#define Pc 256

// SAT stored swizzled: element (r,c) lives at  r*64 + ((c>>2 ^ (r&7))<<2) + (c&3)
__device__ __forceinline__ int swz(int r, int c) {
    return (r << 6) + ((((c >> 2) ^ (r & 7)) << 2) | (c & 3));
}

__global__ __launch_bounds__(256, 8)
void brief_desc_kernel(const float* __restrict__ img,
                       const float* __restrict__ kp,
                       const float* __restrict__ ori,
                       const float* __restrict__ oy1v,
                       const float* __restrict__ ox1v,
                       const float* __restrict__ oy2v,
                       const float* __restrict__ ox2v,
                       const float* __restrict__ thr,
                       const int*   __restrict__ radii,
                       float* __restrict__ out)
{
    __shared__ float S[64 * 64];     // 16 KB, swizzled SAT
    __shared__ float seg[64 * 5];    // column-scan segment totals, stride 5
    __shared__ float red[8];

    const int blk = blockIdx.x;      // b*K + k
    const int b   = blk >> 11;       // Kc = 2048
    const int tid = threadIdx.x;

    // --- pattern constants: issue these loads early (independent of patch) ---
    const float o_y1 = oy1v[tid];
    const float o_x1 = ox1v[tid];
    const float o_y2 = oy2v[tid];
    const float o_x2 = ox2v[tid];
    const float th   = thr[tid];
    const int   rad  = radii[tid];

    // --- keypoint, validity, orientation (broadcast loads) ---
    const float kpy = kp[blk * 2 + 0];
    const float kpx = kp[blk * 2 + 1];
    const float valid = (kpy >= 0.0f) ? 1.0f : 0.0f;
    const float y = fminf(fmaxf(kpy, 0.0f), (float)(Hc - 1));
    const float x = fminf(fmaxf(kpx, 0.0f), (float)(Wc - 1));
    const int iy = (int)rintf(y);    // round-half-even == jnp.round
    const int ix = (int)rintf(x);

    const float* imb = img + (size_t)b * Hc * Wc;
    const float theta = ori[(size_t)b * Hc * Wc + (size_t)iy * Wc + ix];
    float st, ct;
    sincosf(theta, &st, &ct);

    // patch origin; x-origin floored to a multiple of 4 for aligned float4 LDG.
    const int oy0 = iy - 31;
    const int ox0 = (ix - 31) & ~3;

    // ===== Phase A: fused load + row prefix (coalesced float4 + shfl scan) =====
    {
        const int lane16 = tid & 15;          // chunk index within row
        const int grp    = tid >> 4;          // 16 row-groups; warp = 2 rows
        const int k8     = grp & 7;           // (row & 7) is pass-invariant
        const int cs4    = (lane16 ^ k8) << 2;
        const int gxc    = ox0 + (lane16 << 2);
        const bool xok   = (gxc >= 0) & (gxc <= Wc - 4);  // chunks never straddle

        #pragma unroll
        for (int p = 0; p < 4; p++) {
            const int r  = (p << 4) + grp;
            const int gy = oy0 + r;
            float4 e = make_float4(0.f, 0.f, 0.f, 0.f);
            if (xok && gy >= 0 && gy < Hc)
                e = *reinterpret_cast<const float4*>(imb + (size_t)gy * Wc + gxc);

            float v0 = e.x;
            float v1 = v0 + e.y;
            float v2 = v1 + e.z;
            float v3 = v2 + e.w;

            float t = v3;                     // inclusive scan of chunk totals
            #pragma unroll
            for (int d = 1; d < 16; d <<= 1) {
                const float n = __shfl_up_sync(0xffffffffu, t, d, 16);
                if (lane16 >= d) t += n;
            }
            const float off = t - v3;         // exclusive prefix for this chunk

            *reinterpret_cast<float4*>(&S[(r << 6) + cs4]) =
                make_float4(v0 + off, v1 + off, v2 + off, v3 + off);
        }
    }
    __syncthreads();

    // ===== Phase B: column prefix, parallel over 4 segments of 16 rows =====
    // Two-pass re-read scan: no v[16] buffer -> low register pressure.
    {
        const int c  = tid & 63;              // column
        const int q  = tid >> 6;              // row segment 0..3
        const int r0 = q << 4;
        const int cx = c >> 2;
        const int cl = c & 3;

        float s = 0.0f;
        #pragma unroll
        for (int i = 0; i < 16; i++) {
            const int r = r0 + i;
            s += S[(r << 6) + (((cx ^ (r & 7)) << 2) | cl)];
        }
        seg[c * 5 + q] = s;
        __syncthreads();

        float acc = 0.0f;
        #pragma unroll
        for (int qq = 0; qq < 3; qq++)
            if (qq < q) acc += seg[c * 5 + qq];

        #pragma unroll
        for (int i = 0; i < 16; i++) {
            const int r = r0 + i;
            const int a = (r << 6) + (((cx ^ (r & 7)) << 2) | cl);
            acc += S[a];
            S[a] = acc;
        }
    }
    __syncthreads();

    // ===== Phase C: sampling — both test points per thread =====
    const float dn = (float)(2 * rad + 1);
    const float invden = 1.0f / (dn * dn);

    const float p1y = y + (o_x1 * st + o_y1 * ct);
    const float p1x = x + (o_x1 * ct - o_y1 * st);
    const float p2y = y + (o_x2 * st + o_y2 * ct);
    const float p2x = x + (o_x2 * ct - o_y2 * st);

    auto boxavg = [&](float py, float px) -> float {
        // reference order: round first, then clip
        const float jyf = fminf(fmaxf(rintf(py), 0.0f), (float)(Hc - 1));
        const float jxf = fminf(fmaxf(rintf(px), 0.0f), (float)(Wc - 1));
        const int ly = (int)jyf - oy0;        // in [8,54]
        const int lx = (int)jxf - ox0;        // in [8,57]
        const int y1 = ly - rad - 1, y2 = ly + rad;
        const int x1 = lx - rad - 1, x2 = lx + rad;
        const float s = S[swz(y2, x2)] - S[swz(y1, x2)]
                      - S[swz(y2, x1)] + S[swz(y1, x1)];
        return s * invden;
    };

    const float d = boxavg(p1y, p1x) - boxavg(p2y, p2x) - th;

    // ===== Phase D: L2 normalize + write =====
    float sq = d * d;
    #pragma unroll
    for (int off = 16; off; off >>= 1)
        sq += __shfl_xor_sync(0xffffffffu, sq, off);
    if ((tid & 31) == 0) red[tid >> 5] = sq;
    __syncthreads();
    const float tot = red[0] + red[1] + red[2] + red[3]
                    + red[4] + red[5] + red[6] + red[7];
    const float norm  = sqrtf(tot);
    const float scale = valid / fmaxf(norm, 1e-12f);

    out[(size_t)blk * Pc + tid] = d * scale;
}

extern "C" void kernel_launch(void* const* d_in, const int* in_sizes, int n_in,
                              void* d_out, int out_size)
{
    const float* img  = (const float*)d_in[0];  // image (B,1,H,W)
    const float* kp   = (const float*)d_in[1];  // keypoints (B,K,2)
    const float* ori  = (const float*)d_in[2];  // orientation (B,1,H,W)
    const float* oy1  = (const float*)d_in[3];
    const float* ox1  = (const float*)d_in[4];
    const float* oy2  = (const float*)d_in[5];
    const float* ox2  = (const float*)d_in[6];
    const float* thr  = (const float*)d_in[7];
    const int*   rad  = (const int*)d_in[8];
    float* out = (float*)d_out;

    brief_desc_kernel<<<Bc * Kc, Pc>>>(img, kp, ori, oy1, ox1, oy2, ox2, thr, rad, out);
}

// round 12
// speedup vs baseline: 1.0167x; 1.0167x over previous
#include <cuda_runtime.h>
#include <math.h>

#define Bc 2
#define Hc 1080
#define Wc 1920
#define Kc 2048
#define Pc 256

// SAT stored swizzled: element (r,c) lives at  r*64 + ((c>>2 ^ (r&7))<<2) + (c&3)
__device__ __forceinline__ int swz(int r, int c) {
    return (r << 6) + ((((c >> 2) ^ (r & 7)) << 2) | (c & 3));
}

__global__ __launch_bounds__(256, 7)
void brief_desc_kernel(const float* __restrict__ img,
                       const float* __restrict__ kp,
                       const float* __restrict__ ori,
                       const float* __restrict__ oy1v,
                       const float* __restrict__ ox1v,
                       const float* __restrict__ oy2v,
                       const float* __restrict__ ox2v,
                       const float* __restrict__ thr,
                       const int*   __restrict__ radii,
                       float* __restrict__ out)
{
    __shared__ float S[64 * 64];     // 16 KB, swizzled SAT
    __shared__ float seg[64 * 5];    // column-scan segment totals, stride 5
    __shared__ float red[8];

    const int blk = blockIdx.x;      // b*K + k
    const int b   = blk >> 11;       // Kc = 2048
    const int tid = threadIdx.x;

    // --- minimal pre-phase state: patch origin only (keeps regs low in A/B) ---
    int iy, ix;
    {
        const float kpy = kp[blk * 2 + 0];
        const float kpx = kp[blk * 2 + 1];
        iy = (int)rintf(fminf(fmaxf(kpy, 0.0f), (float)(Hc - 1)));
        ix = (int)rintf(fminf(fmaxf(kpx, 0.0f), (float)(Wc - 1)));
    }
    const int oy0 = iy - 31;
    const int ox0 = (ix - 31) & ~3;  // 4-aligned for float4 LDG
    const float* imb = img + (size_t)b * Hc * Wc;

    // ===== Phase A: fused load + row prefix (coalesced float4 + shfl scan) =====
    {
        const int lane16 = tid & 15;          // chunk index within row
        const int grp    = tid >> 4;          // 16 row-groups; warp = 2 rows
        const int k8     = grp & 7;           // (row & 7) is pass-invariant
        const int cs4    = (lane16 ^ k8) << 2;
        const int gxc    = ox0 + (lane16 << 2);
        const bool xok   = (gxc >= 0) & (gxc <= Wc - 4);  // chunks never straddle

        #pragma unroll
        for (int p = 0; p < 4; p++) {
            const int r  = (p << 4) + grp;
            const int gy = oy0 + r;
            float4 e = make_float4(0.f, 0.f, 0.f, 0.f);
            if (xok && gy >= 0 && gy < Hc)
                e = *reinterpret_cast<const float4*>(imb + (size_t)gy * Wc + gxc);

            float v0 = e.x;
            float v1 = v0 + e.y;
            float v2 = v1 + e.z;
            float v3 = v2 + e.w;

            float t = v3;                     // inclusive scan of chunk totals
            #pragma unroll
            for (int d = 1; d < 16; d <<= 1) {
                const float n = __shfl_up_sync(0xffffffffu, t, d, 16);
                if (lane16 >= d) t += n;
            }
            const float off = t - v3;         // exclusive prefix for this chunk

            *reinterpret_cast<float4*>(&S[(r << 6) + cs4]) =
                make_float4(v0 + off, v1 + off, v2 + off, v3 + off);
        }
    }
    __syncthreads();

    // ===== Phase B: column prefix, parallel over 4 segments of 16 rows =====
    // v[16] register-buffered scan (R9 winner): low smem traffic.
    {
        const int c  = tid & 63;              // column
        const int q  = tid >> 6;              // row segment 0..3
        const int r0 = q << 4;
        const int cx = c >> 2;
        const int cl = c & 3;

        float v[16];
        float s = 0.0f;
        #pragma unroll
        for (int i = 0; i < 16; i++) {
            const int r = r0 + i;
            s += S[(r << 6) + (((cx ^ (r & 7)) << 2) | cl)];
            v[i] = s;
        }
        seg[c * 5 + q] = s;
        __syncthreads();

        float off = 0.0f;
        #pragma unroll
        for (int qq = 0; qq < 3; qq++)
            if (qq < q) off += seg[c * 5 + qq];

        #pragma unroll
        for (int i = 0; i < 16; i++) {
            const int r = r0 + i;
            S[(r << 6) + (((cx ^ (r & 7)) << 2) | cl)] = v[i] + off;
        }
    }
    __syncthreads();

    // ===== Phase C: deferred keypoint/pattern state + sampling =====
    const float kpy = kp[blk * 2 + 0];        // broadcast reload (L1-hit)
    const float kpx = kp[blk * 2 + 1];
    const float valid = (kpy >= 0.0f) ? 1.0f : 0.0f;
    const float y = fminf(fmaxf(kpy, 0.0f), (float)(Hc - 1));
    const float x = fminf(fmaxf(kpx, 0.0f), (float)(Wc - 1));

    const float theta = ori[(size_t)b * Hc * Wc + (size_t)iy * Wc + ix];
    float st, ct;
    sincosf(theta, &st, &ct);

    const float o_y1 = oy1v[tid];
    const float o_x1 = ox1v[tid];
    const float o_y2 = oy2v[tid];
    const float o_x2 = ox2v[tid];
    const float th   = thr[tid];
    const int   rad  = radii[tid];
    const float dn   = (float)(2 * rad + 1);
    const float invden = 1.0f / (dn * dn);

    const float p1y = y + (o_x1 * st + o_y1 * ct);
    const float p1x = x + (o_x1 * ct - o_y1 * st);
    const float p2y = y + (o_x2 * st + o_y2 * ct);
    const float p2x = x + (o_x2 * ct - o_y2 * st);

    auto boxavg = [&](float py, float px) -> float {
        // reference order: round first, then clip
        const float jyf = fminf(fmaxf(rintf(py), 0.0f), (float)(Hc - 1));
        const float jxf = fminf(fmaxf(rintf(px), 0.0f), (float)(Wc - 1));
        const int ly = (int)jyf - oy0;        // in [8,54]
        const int lx = (int)jxf - ox0;        // in [8,57]
        const int y1 = ly - rad - 1, y2 = ly + rad;
        const int x1 = lx - rad - 1, x2 = lx + rad;
        const float s = S[swz(y2, x2)] - S[swz(y1, x2)]
                      - S[swz(y2, x1)] + S[swz(y1, x1)];
        return s * invden;
    };

    const float d = boxavg(p1y, p1x) - boxavg(p2y, p2x) - th;

    // ===== Phase D: L2 normalize + write =====
    float sq = d * d;
    #pragma unroll
    for (int off = 16; off; off >>= 1)
        sq += __shfl_xor_sync(0xffffffffu, sq, off);
    if ((tid & 31) == 0) red[tid >> 5] = sq;
    __syncthreads();
    const float tot = red[0] + red[1] + red[2] + red[3]
                    + red[4] + red[5] + red[6] + red[7];
    const float norm  = sqrtf(tot);
    const float scale = valid / fmaxf(norm, 1e-12f);

    out[(size_t)blk * Pc + tid] = d * scale;
}

extern "C" void kernel_launch(void* const* d_in, const int* in_sizes, int n_in,
                              void* d_out, int out_size)
{
    const float* img  = (const float*)d_in[0];  // image (B,1,H,W)
    const float* kp   = (const float*)d_in[1];  // keypoints (B,K,2)
    const float* ori  = (const float*)d_in[2];  // orientation (B,1,H,W)
    const float* oy1  = (const float*)d_in[3];
    const float* ox1  = (const float*)d_in[4];
    const float* oy2  = (const float*)d_in[5];
    const float* ox2  = (const float*)d_in[6];
    const float* thr  = (const float*)d_in[7];
    const int*   rad  = (const int*)d_in[8];
    float* out = (float*)d_out;

    brief_desc_kernel<<<Bc * Kc, Pc>>>(img, kp, ori, oy1, ox1, oy2, ox2, thr, rad, out);
}

// round 13
// speedup vs baseline: 1.0880x; 1.0702x over previous
#include <cuda_runtime.h>
#include <math.h>

#define Bc 2
#define Hc 1080
#define Wc 1920
#define Kc 2048
#define Pc 256

// SAT stored swizzled: element (r,c) lives at  r*64 + ((c>>2 ^ (r&7))<<2) + (c&3)
__device__ __forceinline__ int swz(int r, int c) {
    return (r << 6) + ((((c >> 2) ^ (r & 7)) << 2) | (c & 3));
}

__global__ __launch_bounds__(256, 6)
void brief_desc_kernel(const float* __restrict__ img,
                       const float* __restrict__ kp,
                       const float* __restrict__ ori,
                       const float* __restrict__ oy1v,
                       const float* __restrict__ ox1v,
                       const float* __restrict__ oy2v,
                       const float* __restrict__ ox2v,
                       const float* __restrict__ thr,
                       const int*   __restrict__ radii,
                       float* __restrict__ out)
{
    __shared__ float S[64 * 64];     // 16 KB, swizzled SAT
    __shared__ float seg[64 * 5];    // column-scan segment totals, stride 5
    __shared__ float red[8];

    const int blk = blockIdx.x;      // b*K + k
    const int b   = blk >> 11;       // Kc = 2048
    const int tid = threadIdx.x;

    // --- minimal pre-phase state: patch origin only (keeps regs low in A/B) ---
    int iy, ix;
    {
        const float kpy = kp[blk * 2 + 0];
        const float kpx = kp[blk * 2 + 1];
        iy = (int)rintf(fminf(fmaxf(kpy, 0.0f), (float)(Hc - 1)));
        ix = (int)rintf(fminf(fmaxf(kpx, 0.0f), (float)(Wc - 1)));
    }
    const int oy0 = iy - 31;
    const int ox0 = (ix - 31) & ~3;  // 4-aligned for float4 LDG
    const float* imb = img + (size_t)b * Hc * Wc;

    // ===== Phase A: fused load + row prefix (coalesced float4 + shfl scan) =====
    {
        const int lane16 = tid & 15;          // chunk index within row
        const int grp    = tid >> 4;          // 16 row-groups; warp = 2 rows
        const int k8     = grp & 7;           // (row & 7) is pass-invariant
        const int cs4    = (lane16 ^ k8) << 2;
        const int gxc    = ox0 + (lane16 << 2);
        const bool xok   = (gxc >= 0) & (gxc <= Wc - 4);  // chunks never straddle

        #pragma unroll
        for (int p = 0; p < 4; p++) {
            const int r  = (p << 4) + grp;
            const int gy = oy0 + r;
            float4 e = make_float4(0.f, 0.f, 0.f, 0.f);
            if (xok && gy >= 0 && gy < Hc)
                e = *reinterpret_cast<const float4*>(imb + (size_t)gy * Wc + gxc);

            float v0 = e.x;
            float v1 = v0 + e.y;
            float v2 = v1 + e.z;
            float v3 = v2 + e.w;

            float t = v3;                     // inclusive scan of chunk totals
            #pragma unroll
            for (int d = 1; d < 16; d <<= 1) {
                const float n = __shfl_up_sync(0xffffffffu, t, d, 16);
                if (lane16 >= d) t += n;
            }
            const float off = t - v3;         // exclusive prefix for this chunk

            *reinterpret_cast<float4*>(&S[(r << 6) + cs4]) =
                make_float4(v0 + off, v1 + off, v2 + off, v3 + off);
        }
    }
    __syncthreads();

    // ===== Phase B: column prefix, parallel over 4 segments of 16 rows =====
    // v[16] register-buffered scan (R9 winner) — 40-reg budget avoids spill.
    {
        const int c  = tid & 63;              // column
        const int q  = tid >> 6;              // row segment 0..3
        const int r0 = q << 4;
        const int cx = c >> 2;
        const int cl = c & 3;

        float v[16];
        float s = 0.0f;
        #pragma unroll
        for (int i = 0; i < 16; i++) {
            const int r = r0 + i;
            s += S[(r << 6) + (((cx ^ (r & 7)) << 2) | cl)];
            v[i] = s;
        }
        seg[c * 5 + q] = s;
        __syncthreads();

        float off = 0.0f;
        #pragma unroll
        for (int qq = 0; qq < 3; qq++)
            if (qq < q) off += seg[c * 5 + qq];

        #pragma unroll
        for (int i = 0; i < 16; i++) {
            const int r = r0 + i;
            S[(r << 6) + (((cx ^ (r & 7)) << 2) | cl)] = v[i] + off;
        }
    }
    __syncthreads();

    // ===== Phase C: deferred keypoint/pattern state + sampling =====
    const float kpy = kp[blk * 2 + 0];        // broadcast reload (L1-hit)
    const float kpx = kp[blk * 2 + 1];
    const float valid = (kpy >= 0.0f) ? 1.0f : 0.0f;
    const float y = fminf(fmaxf(kpy, 0.0f), (float)(Hc - 1));
    const float x = fminf(fmaxf(kpx, 0.0f), (float)(Wc - 1));

    const float theta = ori[(size_t)b * Hc * Wc + (size_t)iy * Wc + ix];
    float st, ct;
    sincosf(theta, &st, &ct);

    const float o_y1 = oy1v[tid];
    const float o_x1 = ox1v[tid];
    const float o_y2 = oy2v[tid];
    const float o_x2 = ox2v[tid];
    const float th   = thr[tid];
    const int   rad  = radii[tid];
    const float dn   = (float)(2 * rad + 1);
    const float invden = 1.0f / (dn * dn);

    const float p1y = y + (o_x1 * st + o_y1 * ct);
    const float p1x = x + (o_x1 * ct - o_y1 * st);
    const float p2y = y + (o_x2 * st + o_y2 * ct);
    const float p2x = x + (o_x2 * ct - o_y2 * st);

    auto boxavg = [&](float py, float px) -> float {
        // reference order: round first, then clip
        const float jyf = fminf(fmaxf(rintf(py), 0.0f), (float)(Hc - 1));
        const float jxf = fminf(fmaxf(rintf(px), 0.0f), (float)(Wc - 1));
        const int ly = (int)jyf - oy0;        // in [8,54]
        const int lx = (int)jxf - ox0;        // in [8,57]
        const int y1 = ly - rad - 1, y2 = ly + rad;
        const int x1 = lx - rad - 1, x2 = lx + rad;
        const float s = S[swz(y2, x2)] - S[swz(y1, x2)]
                      - S[swz(y2, x1)] + S[swz(y1, x1)];
        return s * invden;
    };

    const float d = boxavg(p1y, p1x) - boxavg(p2y, p2x) - th;

    // ===== Phase D: L2 normalize + write =====
    float sq = d * d;
    #pragma unroll
    for (int off = 16; off; off >>= 1)
        sq += __shfl_xor_sync(0xffffffffu, sq, off);
    if ((tid & 31) == 0) red[tid >> 5] = sq;
    __syncthreads();
    const float tot = red[0] + red[1] + red[2] + red[3]
                    + red[4] + red[5] + red[6] + red[7];
    const float norm  = sqrtf(tot);
    const float scale = valid / fmaxf(norm, 1e-12f);

    out[(size_t)blk * Pc + tid] = d * scale;
}

extern "C" void kernel_launch(void* const* d_in, const int* in_sizes, int n_in,
                              void* d_out, int out_size)
{
    const float* img  = (const float*)d_in[0];  // image (B,1,H,W)
    const float* kp   = (const float*)d_in[1];  // keypoints (B,K,2)
    const float* ori  = (const float*)d_in[2];  // orientation (B,1,H,W)
    const float* oy1  = (const float*)d_in[3];
    const float* ox1  = (const float*)d_in[4];
    const float* oy2  = (const float*)d_in[5];
    const float* ox2  = (const float*)d_in[6];
    const float* thr  = (const float*)d_in[7];
    const int*   rad  = (const int*)d_in[8];
    float* out = (float*)d_out;

    brief_desc_kernel<<<Bc * Kc, Pc>>>(img, kp, ori, oy1, ox1, oy2, ox2, thr, rad, out);
}